// round 1
// baseline (speedup 1.0000x reference)
#include <cuda_runtime.h>
#include <cfloat>

#define BB 4
#define NN 8192
#define CC 3
#define KK 16
#define DD 64
#define NPTS (BB*NN)
#define NBLK2 256
#define BN_EPS 1e-5f

// ---------------- scratch (static device globals; no allocation) ----------------
__device__ float g_u[NPTS*DD];      // 8 MB : u_i = x_i*(W0-W1)+b
__device__ float g_v[NPTS*DD];      // 8 MB : v_j = x_j*(W1+W2)
__device__ float g_vmax[NPTS*DD];   // 8 MB : per-point channel max of gathered v
__device__ float g_vmin[NPTS*DD];   // 8 MB : per-point channel min of gathered v
__device__ int   g_idx[NPTS*KK];    // 2 MB : knn indices (within batch)
__device__ float g_psum[NBLK2*DD];  // block partial sums of h
__device__ float g_psq[NBLK2*DD];   // block partial sums of h^2
__device__ float g_scale[DD];
__device__ float g_shift[DD];

// ---------------- kernel 0: u, v precompute ----------------
__global__ void uv_kernel(const float* __restrict__ x,
                          const float* __restrict__ W,
                          const float* __restrict__ bias) {
    int gid = blockIdx.x*blockDim.x + threadIdx.x;
    if (gid >= NPTS*DD) return;
    int pt = gid >> 6, d = gid & 63;
    float xc[3];
    xc[0] = __ldg(&x[pt*3+0]);
    xc[1] = __ldg(&x[pt*3+1]);
    xc[2] = __ldg(&x[pt*3+2]);
    float u = __ldg(&bias[d]);
    float v = 0.f;
    #pragma unroll
    for (int c = 0; c < CC; ++c) {
        float w0 = __ldg(&W[c*DD + d]);
        float w1 = __ldg(&W[(CC+c)*DD + d]);
        float w2 = __ldg(&W[(2*CC+c)*DD + d]);
        u = fmaf(xc[c], w0 - w1, u);
        v = fmaf(xc[c], w1 + w2, v);
    }
    g_u[gid] = u;
    g_v[gid] = v;
}

// ---------------- kernel 1: brute-force KNN (k=16) ----------------
// One thread per query point; candidates tiled through shared memory as
// float4(x,y,z,sq). Inner loop is warp-uniform -> broadcast LDS.
// Register-resident sorted top-16 via unrolled bubble insert.
__global__ void __launch_bounds__(256) knn_kernel(const float* __restrict__ x) {
    __shared__ float4 sh[1024];
    int batch = blockIdx.x >> 5;             // 32 blocks per batch
    int qi = ((blockIdx.x & 31) << 8) + threadIdx.x;
    const float* xb = x + (size_t)batch * NN * 3;

    float qx = xb[qi*3+0], qy = xb[qi*3+1], qz = xb[qi*3+2];
    float qsq = fmaf(qz, qz, fmaf(qy, qy, qx*qx));

    float dist[KK];
    int   ind[KK];
    #pragma unroll
    for (int s = 0; s < KK; ++s) { dist[s] = FLT_MAX; ind[s] = 0; }

    for (int t = 0; t < NN/1024; ++t) {
        __syncthreads();
        int base = t << 10;
        #pragma unroll
        for (int r = 0; r < 4; ++r) {
            int c = base + (r << 8) + threadIdx.x;
            float a0 = xb[c*3+0], a1 = xb[c*3+1], a2 = xb[c*3+2];
            sh[(r << 8) + threadIdx.x] =
                make_float4(a0, a1, a2, fmaf(a2, a2, fmaf(a1, a1, a0*a0)));
        }
        __syncthreads();
        #pragma unroll 4
        for (int j = 0; j < 1024; ++j) {
            float4 p = sh[j];
            float dot = fmaf(p.z, qz, fmaf(p.y, qy, p.x*qx));
            // d = sq_i + sq_j - 2*dot  (2*dot exact, single rounding on subtract,
            //  matches reference formula; self-distance exactly 0)
            float dd = fmaf(-2.f, dot, qsq + p.w);
            if (dd < dist[KK-1]) {
                float dv = dd; int jj = base + j;
                #pragma unroll
                for (int s = 0; s < KK; ++s) {
                    if (dv < dist[s]) {
                        float tf = dist[s]; dist[s] = dv; dv = tf;
                        int ti = ind[s]; ind[s] = jj; jj = ti;
                    }
                }
            }
        }
    }

    int* op = g_idx + ((size_t)(batch*NN + qi)) * KK;
    #pragma unroll
    for (int s = 0; s < KK; ++s) op[s] = ind[s];
}

// ---------------- kernel 2: neighbor gather + BN partial stats ----------------
// One warp per point (2 channels per lane). Computes S1=sum v, S2=sum v^2,
// vmax, vmin over the 16 neighbors; accumulates deterministic block partials
// of sum(h) and sum(h^2) with h = u + v.
__global__ void __launch_bounds__(256) gather_stats_kernel() {
    __shared__ float s_sum[8][DD];
    __shared__ float s_sq[8][DD];
    int lane = threadIdx.x & 31;
    int wrp  = threadIdx.x >> 5;
    int gw   = blockIdx.x * 8 + wrp;

    float accs0 = 0.f, accs1 = 0.f, accq0 = 0.f, accq1 = 0.f;

    for (int i = gw; i < NPTS; i += NBLK2*8) {
        int b = i >> 13;                       // i / NN
        int myidx = 0;
        if (lane < KK) myidx = g_idx[(size_t)i*KK + lane];
        float u0 = g_u[(size_t)i*DD + lane];
        float u1 = g_u[(size_t)i*DD + lane + 32];

        float s10 = 0.f, s11 = 0.f, s20 = 0.f, s21 = 0.f;
        float mx0 = -FLT_MAX, mx1 = -FLT_MAX, mn0 = FLT_MAX, mn1 = FLT_MAX;
        #pragma unroll
        for (int n = 0; n < KK; ++n) {
            int j = __shfl_sync(0xffffffffu, myidx, n);
            const float* vp = g_v + ((size_t)(b*NN + j)) * DD;
            float va = vp[lane], vb = vp[lane+32];
            s10 += va; s11 += vb;
            s20 = fmaf(va, va, s20); s21 = fmaf(vb, vb, s21);
            mx0 = fmaxf(mx0, va); mx1 = fmaxf(mx1, vb);
            mn0 = fminf(mn0, va); mn1 = fminf(mn1, vb);
        }
        g_vmax[(size_t)i*DD + lane]      = mx0;
        g_vmax[(size_t)i*DD + lane + 32] = mx1;
        g_vmin[(size_t)i*DD + lane]      = mn0;
        g_vmin[(size_t)i*DD + lane + 32] = mn1;

        accs0 += fmaf((float)KK, u0, s10);
        accs1 += fmaf((float)KK, u1, s11);
        accq0 += (float)KK*u0*u0 + 2.f*u0*s10 + s20;
        accq1 += (float)KK*u1*u1 + 2.f*u1*s11 + s21;
    }

    s_sum[wrp][lane]      = accs0;
    s_sum[wrp][lane + 32] = accs1;
    s_sq[wrp][lane]       = accq0;
    s_sq[wrp][lane + 32]  = accq1;
    __syncthreads();

    if (threadIdx.x < DD) {
        float s = 0.f;
        #pragma unroll
        for (int k = 0; k < 8; ++k) s += s_sum[k][threadIdx.x];
        g_psum[blockIdx.x*DD + threadIdx.x] = s;
    } else if (threadIdx.x < 2*DD) {
        int d = threadIdx.x - DD;
        float s = 0.f;
        #pragma unroll
        for (int k = 0; k < 8; ++k) s += s_sq[k][d];
        g_psq[blockIdx.x*DD + d] = s;
    }
}

// ---------------- kernel 3: finalize BN stats -> scale/shift ----------------
__global__ void stats_kernel(const float* __restrict__ gamma,
                             const float* __restrict__ beta) {
    int t = threadIdx.x;
    if (t >= DD) return;
    float s = 0.f, q = 0.f;
    for (int k = 0; k < NBLK2; ++k) { s += g_psum[k*DD + t]; q += g_psq[k*DD + t]; }
    const float inv = 1.f / (float)((size_t)NPTS * KK);
    float mean = s * inv;
    float var  = q * inv - mean*mean;
    float sc   = __ldg(&gamma[t]) * rsqrtf(var + BN_EPS);
    g_scale[t] = sc;
    g_shift[t] = __ldg(&beta[t]) - mean * sc;
}

// ---------------- kernel 4: normalize + relu + (folded) max-pool ----------------
// max_k relu(sc*(u+v_k)+sh) == relu(sc*(u + max_k v)+sh) for sc>=0 (min for sc<0).
__global__ void out_kernel(float* __restrict__ out) {
    int gid = blockIdx.x*blockDim.x + threadIdx.x;
    if (gid >= NPTS*DD) return;
    int d = gid & 63;
    float sc = g_scale[d];
    float vsel = (sc >= 0.f) ? g_vmax[gid] : g_vmin[gid];
    float h = fmaf(sc, g_u[gid] + vsel, g_shift[d]);
    out[gid] = fmaxf(h, 0.f);
}

// ---------------- launch ----------------
extern "C" void kernel_launch(void* const* d_in, const int* in_sizes, int n_in,
                              void* d_out, int out_size) {
    const float* x     = (const float*)d_in[0];
    const float* W     = (const float*)d_in[1];
    const float* b     = (const float*)d_in[2];
    const float* gamma = (const float*)d_in[3];
    const float* beta  = (const float*)d_in[4];
    float* out = (float*)d_out;

    uv_kernel<<<(NPTS*DD)/256, 256>>>(x, W, b);
    knn_kernel<<<BB*(NN/256), 256>>>(x);
    gather_stats_kernel<<<NBLK2, 256>>>();
    stats_kernel<<<1, 64>>>(gamma, beta);
    out_kernel<<<(NPTS*DD)/256, 256>>>(out);
}

// round 6
// speedup vs baseline: 1.1622x; 1.1622x over previous
#include <cuda_runtime.h>
#include <cfloat>

#define BB 4
#define NN 8192
#define KK 16
#define DD 64
#define NPTS (BB*NN)
#define GRID 48
#define CELLS (GRID*GRID*GRID)          // 110592
#define TOTCELLS (BB*CELLS)             // 442368 = 432*1024
#define NSCAN1 (TOTCELLS/1024)          // 432
#define ORG  (-6.144f)
#define HCEL (0.256f)
#define INVH (3.90625f)
#define NBLK2 256
#define BN_EPS 1e-5f

// ---------------- static scratch (no allocation) ----------------
__device__ int    g_cnt[TOTCELLS];      // histogram, then countdown cursor
__device__ int    g_start[TOTCELLS+1];  // global exclusive prefix
__device__ int    g_bsum[NSCAN1];
__device__ int    g_bsum2[NSCAN1];
__device__ int    g_pcell[NPTS];
__device__ float4 g_spos[NPTS];         // cell-sorted (x,y,z, bitcast local idx)
__device__ int    g_idx[NPTS*KK];       // knn neighbor lists (local idx)
__device__ float  g_a[NPTS*DD];         // u + max_k v
__device__ float  g_b2[NPTS*DD];        // u + min_k v
__device__ float  g_psum[NBLK2*DD];
__device__ float  g_psq[NBLK2*DD];
__device__ float  g_scale[DD];
__device__ float  g_shift[DD];

// ---------------- grid build ----------------
__global__ void zero_cnt_kernel() {
    g_cnt[blockIdx.x*1024 + threadIdx.x] = 0;
}

__global__ void hist_kernel(const float* __restrict__ x) {
    int p = blockIdx.x*256 + threadIdx.x;
    float px = x[p*3+0], py = x[p*3+1], pz = x[p*3+2];
    int cx = min(GRID-1, max(0, (int)floorf((px-ORG)*INVH)));
    int cy = min(GRID-1, max(0, (int)floorf((py-ORG)*INVH)));
    int cz = min(GRID-1, max(0, (int)floorf((pz-ORG)*INVH)));
    int cid = (cz*GRID + cy)*GRID + cx;
    g_pcell[p] = cid;
    atomicAdd(&g_cnt[(p>>13)*CELLS + cid], 1);
}

__global__ void scan1_kernel() {
    __shared__ int s[1024];
    int t = threadIdx.x;
    int g = blockIdx.x*1024 + t;
    int v = g_cnt[g];
    s[t] = v; __syncthreads();
    #pragma unroll
    for (int o = 1; o < 1024; o <<= 1) {
        int a = (t >= o) ? s[t-o] : 0;
        __syncthreads(); s[t] += a; __syncthreads();
    }
    g_start[g] = s[t] - v;
    if (t == 1023) g_bsum[blockIdx.x] = s[t];
}

__global__ void scan2_kernel() {
    __shared__ int s[512];
    int t = threadIdx.x;
    int v = (t < NSCAN1) ? g_bsum[t] : 0;
    s[t] = v; __syncthreads();
    #pragma unroll
    for (int o = 1; o < 512; o <<= 1) {
        int a = (t >= o) ? s[t-o] : 0;
        __syncthreads(); s[t] += a; __syncthreads();
    }
    if (t < NSCAN1) g_bsum2[t] = s[t] - v;
}

__global__ void scan3_kernel() {
    int g = blockIdx.x*1024 + threadIdx.x;
    g_start[g] += g_bsum2[blockIdx.x];
    if (g == 0) g_start[TOTCELLS] = NPTS;
}

__global__ void scatter_kernel(const float* __restrict__ x) {
    int p = blockIdx.x*256 + threadIdx.x;
    int gc = (p>>13)*CELLS + g_pcell[p];
    int pos = atomicAdd(&g_cnt[gc], -1) - 1;
    int slot = g_start[gc] + pos;
    g_spos[slot] = make_float4(x[p*3+0], x[p*3+1], x[p*3+2],
                               __int_as_float(p & (NN-1)));
}

// ---------------- grid KNN (exact, k=16) ----------------
__device__ __forceinline__ unsigned fkey(float d) {
    unsigned s = __float_as_uint(d);
    return s ^ (unsigned)(((int)s >> 31) | 0x80000000);
}
__device__ __forceinline__ float unfkey(unsigned u) {
    unsigned s = (u & 0x80000000u) ? (u ^ 0x80000000u) : ~u;
    return __uint_as_float(s);
}

__global__ void __launch_bounds__(256) knn_grid_kernel() {
    int t = blockIdx.x*256 + threadIdx.x;     // global sorted slot
    int b = t >> 13;
    float4 q = g_spos[t];
    float qx = q.x, qy = q.y, qz = q.z;
    float qsq = fmaf(qz, qz, fmaf(qy, qy, qx*qx));
    int qi = __float_as_int(q.w);
    int cx = min(GRID-1, max(0, (int)floorf((qx-ORG)*INVH)));
    int cy = min(GRID-1, max(0, (int)floorf((qy-ORG)*INVH)));
    int cz = min(GRID-1, max(0, (int)floorf((qz-ORG)*INVH)));

    unsigned long long keys[KK];
    #pragma unroll
    for (int s = 0; s < KK; ++s) keys[s] = ~0ull;
    float d15 = FLT_MAX;
    const int cbase = b*CELLS;

    auto scan_row = [&](int z, int y, int x0, int x1) {
        x0 = max(x0, 0); x1 = min(x1, GRID-1);
        if (x0 > x1) return;
        int rb = cbase + (z*GRID + y)*GRID;
        int s0 = g_start[rb + x0];
        int s1 = g_start[rb + x1 + 1];
        for (int s = s0; s < s1; ++s) {
            float4 p = g_spos[s];
            float sqj = fmaf(p.z, p.z, fmaf(p.y, p.y, p.x*p.x));
            float dot = fmaf(p.z, qz, fmaf(p.y, qy, p.x*qx));
            float dd  = fmaf(-2.f, dot, qsq + sqj);   // same formula as reference
            unsigned long long key =
                ((unsigned long long)fkey(dd) << 32) | (unsigned)__float_as_int(p.w);
            if (key < keys[KK-1]) {
                #pragma unroll
                for (int i2 = 0; i2 < KK; ++i2) {
                    if (key < keys[i2]) {
                        unsigned long long tmp = keys[i2]; keys[i2] = key; key = tmp;
                    }
                }
                d15 = unfkey((unsigned)(keys[KK-1] >> 32));
            }
        }
    };

    // initial 3x3x3 box (R = 1)
    for (int z = max(cz-1, 0); z <= min(cz+1, GRID-1); ++z)
        for (int y = max(cy-1, 0); y <= min(cy+1, GRID-1); ++y)
            scan_row(z, y, cx-1, cx+1);

    int R = 1;
    while (true) {
        // exact stop bound: min distance from q to any unprocessed cell
        int x0 = cx-R, x1 = cx+R, y0 = cy-R, y1 = cy+R, z0 = cz-R, z1 = cz+R;
        float m = 1e30f;
        if (x0 > 0)      m = fminf(m, qx - (ORG + x0*HCEL));
        if (x1 < GRID-1) m = fminf(m, (ORG + (x1+1)*HCEL) - qx);
        if (y0 > 0)      m = fminf(m, qy - (ORG + y0*HCEL));
        if (y1 < GRID-1) m = fminf(m, (ORG + (y1+1)*HCEL) - qy);
        if (z0 > 0)      m = fminf(m, qz - (ORG + z0*HCEL));
        if (z1 < GRID-1) m = fminf(m, (ORG + (z1+1)*HCEL) - qz);
        if (d15 <= m*m) break;   // m=1e30 -> m*m=inf -> also exits on full coverage
        ++R;
        for (int dz = -R; dz <= R; ++dz) {
            int z = cz + dz; if (z < 0 || z >= GRID) continue;
            bool zface = (dz == -R) || (dz == R);
            for (int dy = -R; dy <= R; ++dy) {
                int y = cy + dy; if (y < 0 || y >= GRID) continue;
                if (zface || dy == -R || dy == R) {
                    scan_row(z, y, cx-R, cx+R);
                } else {
                    scan_row(z, y, cx-R, cx-R);
                    scan_row(z, y, cx+R, cx+R);
                }
            }
        }
    }

    long long ob = ((long long)(b*NN + qi))*KK;
    #pragma unroll
    for (int s = 0; s < KK; ++s) g_idx[ob + s] = (int)(keys[s] & 0xFFFFFFFFull);
}

// ---------------- gather + BN partial stats (v computed on the fly) ----------------
__global__ void __launch_bounds__(256) gather_stats_kernel(
        const float* __restrict__ x, const float* __restrict__ W,
        const float* __restrict__ bias) {
    __shared__ float s_sum[8][DD];
    __shared__ float s_sq[8][DD];
    int lane = threadIdx.x & 31;
    int wrp  = threadIdx.x >> 5;
    int gw   = blockIdx.x*8 + wrp;
    int c0 = lane, c1 = lane + 32;

    float ws0[3], ws1[3], wd0[3], wd1[3];
    #pragma unroll
    for (int c = 0; c < 3; ++c) {
        ws0[c] = __ldg(&W[(3+c)*DD + c0]) + __ldg(&W[(6+c)*DD + c0]);
        ws1[c] = __ldg(&W[(3+c)*DD + c1]) + __ldg(&W[(6+c)*DD + c1]);
        wd0[c] = __ldg(&W[c*DD + c0]) - __ldg(&W[(3+c)*DD + c0]);
        wd1[c] = __ldg(&W[c*DD + c1]) - __ldg(&W[(3+c)*DD + c1]);
    }
    float b0 = __ldg(&bias[c0]), b1 = __ldg(&bias[c1]);

    float accs0 = 0.f, accs1 = 0.f, accq0 = 0.f, accq1 = 0.f;

    for (int i = gw; i < NPTS; i += NBLK2*8) {
        int b  = i >> 13;
        int qi = i & (NN-1);
        const float* xb = x + (size_t)b*NN*3;
        float qx2 = xb[qi*3+0], qy2 = xb[qi*3+1], qz2 = xb[qi*3+2];
        float u0 = fmaf(qz2, wd0[2], fmaf(qy2, wd0[1], fmaf(qx2, wd0[0], b0)));
        float u1 = fmaf(qz2, wd1[2], fmaf(qy2, wd1[1], fmaf(qx2, wd1[0], b1)));

        int nid = g_idx[(size_t)i*KK + (lane & 15)];
        float nx = xb[nid*3+0], ny = xb[nid*3+1], nz = xb[nid*3+2];

        float s10 = 0.f, s11 = 0.f, s20 = 0.f, s21 = 0.f;
        float mx0 = -FLT_MAX, mx1 = -FLT_MAX, mn0 = FLT_MAX, mn1 = FLT_MAX;
        #pragma unroll
        for (int n = 0; n < KK; ++n) {
            float xn = __shfl_sync(0xffffffffu, nx, n);
            float yn = __shfl_sync(0xffffffffu, ny, n);
            float zn = __shfl_sync(0xffffffffu, nz, n);
            float v0 = fmaf(zn, ws0[2], fmaf(yn, ws0[1], xn*ws0[0]));
            float v1 = fmaf(zn, ws1[2], fmaf(yn, ws1[1], xn*ws1[0]));
            s10 += v0; s20 = fmaf(v0, v0, s20);
            mx0 = fmaxf(mx0, v0); mn0 = fminf(mn0, v0);
            s11 += v1; s21 = fmaf(v1, v1, s21);
            mx1 = fmaxf(mx1, v1); mn1 = fminf(mn1, v1);
        }
        size_t o = (size_t)i*DD;
        g_a[o + c0]  = u0 + mx0;  g_a[o + c1]  = u1 + mx1;
        g_b2[o + c0] = u0 + mn0;  g_b2[o + c1] = u1 + mn1;

        accs0 += fmaf((float)KK, u0, s10);
        accs1 += fmaf((float)KK, u1, s11);
        accq0 += (float)KK*u0*u0 + 2.f*u0*s10 + s20;
        accq1 += (float)KK*u1*u1 + 2.f*u1*s11 + s21;
    }

    s_sum[wrp][c0] = accs0;  s_sum[wrp][c1] = accs1;
    s_sq[wrp][c0]  = accq0;  s_sq[wrp][c1]  = accq1;
    __syncthreads();

    if (threadIdx.x < DD) {
        float s = 0.f;
        #pragma unroll
        for (int k = 0; k < 8; ++k) s += s_sum[k][threadIdx.x];
        g_psum[blockIdx.x*DD + threadIdx.x] = s;
    } else if (threadIdx.x < 2*DD) {
        int d = threadIdx.x - DD;
        float s = 0.f;
        #pragma unroll
        for (int k = 0; k < 8; ++k) s += s_sq[k][d];
        g_psq[blockIdx.x*DD + d] = s;
    }
}

// ---------------- finalize BN stats (parallel) ----------------
__global__ void stats_kernel(const float* __restrict__ gamma,
                             const float* __restrict__ beta) {
    __shared__ float ss[4][DD];
    __shared__ float sq[4][DD];
    int t = threadIdx.x;          // 256
    int d = t & 63, ch = t >> 6;
    float s = 0.f, q = 0.f;
    for (int k = ch; k < NBLK2; k += 4) {
        s += g_psum[k*DD + d];
        q += g_psq[k*DD + d];
    }
    ss[ch][d] = s; sq[ch][d] = q;
    __syncthreads();
    if (t < DD) {
        float S = ss[0][t] + ss[1][t] + ss[2][t] + ss[3][t];
        float Q = sq[0][t] + sq[1][t] + sq[2][t] + sq[3][t];
        const float inv = 1.f / (float)((long long)NPTS * KK);
        float mean = S * inv;
        float var  = Q * inv - mean*mean;
        float sc   = __ldg(&gamma[t]) * rsqrtf(var + BN_EPS);
        g_scale[t] = sc;
        g_shift[t] = __ldg(&beta[t]) - mean * sc;
    }
}

// ---------------- output: BN affine + relu + folded max-pool ----------------
__global__ void out_kernel(float* __restrict__ out) {
    int gid = blockIdx.x*256 + threadIdx.x;
    int d = gid & 63;
    float sc = g_scale[d];
    float val = (sc >= 0.f) ? g_a[gid] : g_b2[gid];
    out[gid] = fmaxf(fmaf(sc, val, g_shift[d]), 0.f);
}

// ---------------- launch ----------------
extern "C" void kernel_launch(void* const* d_in, const int* in_sizes, int n_in,
                              void* d_out, int out_size) {
    const float* x     = (const float*)d_in[0];
    const float* W     = (const float*)d_in[1];
    const float* b     = (const float*)d_in[2];
    const float* gamma = (const float*)d_in[3];
    const float* beta  = (const float*)d_in[4];
    float* out = (float*)d_out;

    zero_cnt_kernel<<<NSCAN1, 1024>>>();
    hist_kernel<<<NPTS/256, 256>>>(x);
    scan1_kernel<<<NSCAN1, 1024>>>();
    scan2_kernel<<<1, 512>>>();
    scan3_kernel<<<NSCAN1, 1024>>>();
    scatter_kernel<<<NPTS/256, 256>>>(x);
    knn_grid_kernel<<<NPTS/256, 256>>>();
    gather_stats_kernel<<<NBLK2, 256>>>(x, W, b);
    stats_kernel<<<1, 256>>>(gamma, beta);
    out_kernel<<<(NPTS*DD)/256, 256>>>(out);
}